// round 3
// baseline (speedup 1.0000x reference)
#include <cuda_runtime.h>

// XrayTransforms: standardize -> soft-hist equalize -> 2x bilinear (=2x2 avg) -> normalize
// x: (2,1,512,512) f32, out: (2,1,256,256) f32
//
// Strategy (round 3):
//   - count-only fine histogram: 8192 sub-bins (32 per output bin), 1 shared
//     atomic per pixel. Gaussian conv in k_post reconstructs the soft hist
//     (first-order error ~5e-5, stochastic).
//   - non-atomic block partials everywhere; no init kernel.
//   - equalize tabulated on 8192-pt grid; k_out = 2x2 avg of table lerps.

#define NB 256
#define HW 512
#define NPIX (HW*HW)            // 262144 per batch
#define SUBN 8192
#define SUBSCALE 8160.0f        // 255*32 sub-bins across [0,1]
#define BETA 7.5091258e-5f      // A / 8160^2, A = 5000
#define EXPM32B 0.99759997f     // exp(-32*BETA)
#define MRAD 420                // conv radius in sub-bins (13.1 bins)
#define TABN 8192
#define NMM 128                 // minmax blocks
#define HBLKN 74                // hist blocks per batch
#define RADIUS 12
#define TWO_A_D  39.21568627450980f   // 2*A*Delta (Delta = 1/255)
#define A_D2     0.07689350249903883f // A*Delta^2
#define RATIO_C  0.85745500f          // exp(-2*A*Delta^2)
#define INV255   (1.0f/255.0f)

__device__ float g_pmin[NMM];
__device__ float g_pmax[NMM];
__device__ float g_scale[2];                 // [0]=min, [1]=1/(max-min+1e-6)
__device__ float g_part[2][HBLKN][SUBN];     // per-block fine-hist partials
__device__ float g_mom[2][SUBN];             // reduced fine hist
__device__ float g_cdfn[2][NB];
__device__ float g_eqtab[2][TABN];

__global__ void k_minmax(const float* __restrict__ x) {
    __shared__ float smn[256], smx[256];
    const float4* x4 = (const float4*)x;
    int base = blockIdx.x * 1024 + threadIdx.x;     // 131072 float4 / 128 blocks
    float mn = 1e30f, mx = -1e30f;
    #pragma unroll
    for (int q = 0; q < 4; q++) {
        float4 v = x4[base + q * 256];
        mn = fminf(mn, fminf(fminf(v.x, v.y), fminf(v.z, v.w)));
        mx = fmaxf(mx, fmaxf(fmaxf(v.x, v.y), fmaxf(v.z, v.w)));
    }
    smn[threadIdx.x] = mn; smx[threadIdx.x] = mx;
    __syncthreads();
    for (int o = 128; o; o >>= 1) {
        if (threadIdx.x < o) {
            smn[threadIdx.x] = fminf(smn[threadIdx.x], smn[threadIdx.x + o]);
            smx[threadIdx.x] = fmaxf(smx[threadIdx.x], smx[threadIdx.x + o]);
        }
        __syncthreads();
    }
    if (threadIdx.x == 0) { g_pmin[blockIdx.x] = smn[0]; g_pmax[blockIdx.x] = smx[0]; }
}

// 1 shared atomic per pixel into 8192 fine sub-bins; non-atomic flush to g_part.
__global__ void k_hist(const float* __restrict__ x) {
    __shared__ float sh[SUBN];                 // 32KB
    __shared__ float smm[256];
    const int t = threadIdx.x;
    // reduce min/max partials (every block does it; cheap L2 hits)
    smm[t] = (t < NMM) ? g_pmin[t] : 1e30f;
    __syncthreads();
    for (int o = 128; o; o >>= 1) { if (t < o) smm[t] = fminf(smm[t], smm[t + o]); __syncthreads(); }
    const float mn = smm[0];
    __syncthreads();
    smm[t] = (t < NMM) ? g_pmax[t] : -1e30f;
    __syncthreads();
    for (int o = 128; o; o >>= 1) { if (t < o) smm[t] = fmaxf(smm[t], smm[t + o]); __syncthreads(); }
    const float inv = 1.0f / (smm[0] - mn + 1e-6f);
    if (blockIdx.x == 0 && blockIdx.y == 0 && t == 0) { g_scale[0] = mn; g_scale[1] = inv; }
    __syncthreads();

    for (int i = t; i < SUBN; i += blockDim.x) sh[i] = 0.0f;
    __syncthreads();

    const int b = blockIdx.y;
    const float4* xb = (const float4*)(x + b * NPIX);
    const int n4 = NPIX / 4;
    const int stride = gridDim.x * blockDim.x;
    for (int idx = blockIdx.x * blockDim.x + t; idx < n4; idx += stride) {
        float4 p4 = xb[idx];
        float vv[4] = {p4.x, p4.y, p4.z, p4.w};
        #pragma unroll
        for (int q = 0; q < 4; q++) {
            float v = (vv[q] - mn) * inv;
            int i = __float2int_rn(v * SUBSCALE);
            atomicAdd(&sh[i], 1.0f);
        }
    }
    __syncthreads();
    float* dst = g_part[b][blockIdx.x];
    for (int i = t; i < SUBN; i += blockDim.x) dst[i] = sh[i];
}

// 32768 threads; two threads per output element, 37 partials each, pair-combine.
__global__ void k_reduce() {
    __shared__ float s[256];
    int t = blockIdx.x * blockDim.x + threadIdx.x;   // 128*256 = 32768
    int o = t >> 1;                                   // output element 0..16383
    int half = t & 1;
    int b = o >> 13;                                  // /SUBN
    int e = o & (SUBN - 1);
    const float* p = &g_part[b][0][e];
    float sum = 0.0f;
    int k0 = half * 37;
    #pragma unroll 8
    for (int k = 0; k < 37; k++) sum += p[(k0 + k) * SUBN];
    s[threadIdx.x] = sum;
    __syncthreads();
    if ((threadIdx.x & 1) == 0)
        g_mom[b][e] = s[threadIdx.x] + s[threadIdx.x + 1];
}

// fine hist -> Gaussian conv (4-way split per bin) -> scan -> cdfn
__global__ void k_post() {
    __shared__ float s_m[SUBN];        // 32KB
    __shared__ float s_part[4 * NB];
    __shared__ float s_scan[NB];
    const int b = blockIdx.x;
    const int tid = threadIdx.x;       // 1024 threads
    const int j = tid & 255;
    const int q = tid >> 8;
    for (int i = tid; i < SUBN; i += 1024) s_m[i] = g_mom[b][i];
    __syncthreads();

    int c = 32 * j;
    int mlo = (-MRAD < -c) ? -c : -MRAD;
    int mhi = (MRAD > 8160 - c) ? (8160 - c) : MRAD;
    float h = 0.0f;
    int m0 = mlo + q;
    if (m0 <= mhi) {
        float fm = (float)m0;
        float w  = __expf(-BETA * fm * fm);
        float r4 = __expf(-BETA * (8.0f * fm + 16.0f));
        for (int m = m0; m <= mhi; m += 4) {
            h += w * s_m[c + m];
            w *= r4;
            r4 *= EXPM32B;
        }
    }
    s_part[q * NB + j] = h;
    __syncthreads();
    if (tid < NB)
        s_scan[tid] = s_part[tid] + s_part[NB + tid] + s_part[2 * NB + tid] + s_part[3 * NB + tid];
    __syncthreads();
    #pragma unroll
    for (int o = 1; o < NB; o <<= 1) {
        float add = (tid < NB && tid >= o) ? s_scan[tid - o] : 0.0f;
        __syncthreads();
        if (tid < NB) s_scan[tid] += add;
        __syncthreads();
    }
    if (tid < NB) {
        float total = s_scan[NB - 1];
        float invS  = 1.0f / (total + 1e-10f);
        float cdf   = s_scan[tid] * invS;
        float cdf0  = s_scan[0] * invS;
        g_cdfn[b][tid] = (cdf - cdf0) / (1.0f - cdf0 + 1e-10f);
    }
}

// Tabulate eq(v) on TABN grid points over v in [0,1].
__global__ void k_table() {
    __shared__ float cdfn[NB];
    const int b = blockIdx.y;
    for (int i = threadIdx.x; i < NB; i += blockDim.x) cdfn[i] = g_cdfn[b][i];
    __syncthreads();

    int p = blockIdx.x * blockDim.x + threadIdx.x;   // 0..TABN-1
    float v = (float)p * (1.0f / (float)(TABN - 1));
    int k = __float2int_rn(v * 255.0f);
    int jlo = k - RADIUS;
    float d0 = v - (float)jlo * INV255;
    float w = __expf(-5000.0f * d0 * d0);
    float r = __expf(TWO_A_D * d0 - A_D2);
    float num = 0.0f, den = 0.0f;
    #pragma unroll
    for (int s = 0; s < 2 * RADIUS + 1; s++) {
        int j = jlo + s;
        if (j >= 0 && j < NB) {
            num += w * cdfn[j];
            den += w;
        }
        w *= r;
        r *= RATIO_C;
    }
    g_eqtab[b][p] = num / (den + 1e-10f);
}

__device__ __forceinline__ float eq_lerp(float xraw, float mn, float inv,
                                         const float* __restrict__ tb) {
    float v = (xraw - mn) * inv;
    float t = v * (float)(TABN - 1);
    int i0 = (int)t;
    float f = t - (float)i0;
    float e0 = __ldg(tb + i0);
    float e1 = __ldg(tb + i0 + 1);
    return fmaf(f, e1 - e0, e0);
}

__global__ void k_out(const float* __restrict__ x, float* __restrict__ out) {
    int idx = blockIdx.x * blockDim.x + threadIdx.x;   // 131072 output pixels
    int b = idx >> 16;
    int rem = idx & 0xFFFF;
    int oy = rem >> 8;
    int ox = rem & 255;
    const float* base = x + b * NPIX;
    float2 t0 = ((const float2*)(base + (2 * oy)     * HW))[ox];
    float2 t1 = ((const float2*)(base + (2 * oy + 1) * HW))[ox];

    const float mn  = g_scale[0];
    const float inv = g_scale[1];
    const float* tb = g_eqtab[b];
    float e = eq_lerp(t0.x, mn, inv, tb)
            + eq_lerp(t0.y, mn, inv, tb)
            + eq_lerp(t1.x, mn, inv, tb)
            + eq_lerp(t1.y, mn, inv, tb);
    out[idx] = (0.25f * e - 0.15f) / 0.1f;
}

extern "C" void kernel_launch(void* const* d_in, const int* in_sizes, int n_in,
                              void* d_out, int out_size) {
    const float* x = (const float*)d_in[0];
    float* out = (float*)d_out;
    k_minmax<<<NMM, 256>>>(x);
    k_hist<<<dim3(HBLKN, 2), 256>>>(x);
    k_reduce<<<128, 256>>>();
    k_post<<<2, 1024>>>();
    k_table<<<dim3(TABN / 256, 2), 256>>>();
    k_out<<<512, 256>>>(x, out);
}

// round 5
// speedup vs baseline: 3.4385x; 3.4385x over previous
#include <cuda_runtime.h>

// XrayTransforms: standardize -> soft-hist equalize -> 2x bilinear (=2x2 avg) -> normalize
// x: (2,1,512,512) f32, out: (2,1,256,256) f32
//
// Round 5 (= round 4 retry + k_table folded into k_post):
//   - count-only fine histogram (8192 sub-bins, 1 shared atomic/px)
//   - k_post: warp-per-bin / lane-per-tap Gaussian conv (conflict-free LDS),
//     scan -> cdfn, then tabulates eq(v) on an 8192-pt grid in the same block.
//   - k_out = 2x2 average of table lerps.

#define NB 256
#define HW 512
#define NPIX (HW*HW)            // 262144 per batch
#define SUBN 8192
#define SUBSCALE 8160.0f        // 255*32 sub-bins across [0,1]
#define BETA 7.5091258e-5f      // A / 8160^2, A = 5000
#define MRAD 420                // conv radius in sub-bins (13.1 bins)
#define STEP32_C 0.85745500f    // exp(-2048*BETA) = exp(-2*A*Delta^2)
#define TABN 8192
#define NMM 128                 // minmax blocks
#define HBLKN 74                // hist blocks per batch
#define RADIUS 12
#define TWO_A_D  39.21568627450980f   // 2*A*Delta (Delta = 1/255)
#define A_D2     0.07689350249903883f // A*Delta^2
#define RATIO_C  0.85745500f          // exp(-2*A*Delta^2)
#define INV255   (1.0f/255.0f)

__device__ float g_pmin[NMM];
__device__ float g_pmax[NMM];
__device__ float g_scale[2];                 // [0]=min, [1]=1/(max-min+1e-6)
__device__ float g_part[2][HBLKN][SUBN];     // per-block fine-hist partials
__device__ float g_mom[2][SUBN];             // reduced fine hist
__device__ float g_eqtab[2][TABN];

__global__ void k_minmax(const float* __restrict__ x) {
    __shared__ float smn[256], smx[256];
    const float4* x4 = (const float4*)x;
    int base = blockIdx.x * 1024 + threadIdx.x;     // 131072 float4 / 128 blocks
    float mn = 1e30f, mx = -1e30f;
    #pragma unroll
    for (int q = 0; q < 4; q++) {
        float4 v = x4[base + q * 256];
        mn = fminf(mn, fminf(fminf(v.x, v.y), fminf(v.z, v.w)));
        mx = fmaxf(mx, fmaxf(fmaxf(v.x, v.y), fmaxf(v.z, v.w)));
    }
    smn[threadIdx.x] = mn; smx[threadIdx.x] = mx;
    __syncthreads();
    for (int o = 128; o; o >>= 1) {
        if (threadIdx.x < o) {
            smn[threadIdx.x] = fminf(smn[threadIdx.x], smn[threadIdx.x + o]);
            smx[threadIdx.x] = fmaxf(smx[threadIdx.x], smx[threadIdx.x + o]);
        }
        __syncthreads();
    }
    if (threadIdx.x == 0) { g_pmin[blockIdx.x] = smn[0]; g_pmax[blockIdx.x] = smx[0]; }
}

// 1 shared atomic per pixel into 8192 fine sub-bins; non-atomic flush to g_part.
__global__ void k_hist(const float* __restrict__ x) {
    __shared__ float sh[SUBN];                 // 32KB
    __shared__ float smm[256];
    const int t = threadIdx.x;
    smm[t] = (t < NMM) ? g_pmin[t] : 1e30f;
    __syncthreads();
    for (int o = 128; o; o >>= 1) { if (t < o) smm[t] = fminf(smm[t], smm[t + o]); __syncthreads(); }
    const float mn = smm[0];
    __syncthreads();
    smm[t] = (t < NMM) ? g_pmax[t] : -1e30f;
    __syncthreads();
    for (int o = 128; o; o >>= 1) { if (t < o) smm[t] = fmaxf(smm[t], smm[t + o]); __syncthreads(); }
    const float inv = 1.0f / (smm[0] - mn + 1e-6f);
    if (blockIdx.x == 0 && blockIdx.y == 0 && t == 0) { g_scale[0] = mn; g_scale[1] = inv; }
    __syncthreads();

    for (int i = t; i < SUBN; i += blockDim.x) sh[i] = 0.0f;
    __syncthreads();

    const int b = blockIdx.y;
    const float4* xb = (const float4*)(x + b * NPIX);
    const int n4 = NPIX / 4;
    const int stride = gridDim.x * blockDim.x;
    for (int idx = blockIdx.x * blockDim.x + t; idx < n4; idx += stride) {
        float4 p4 = xb[idx];
        float vv[4] = {p4.x, p4.y, p4.z, p4.w};
        #pragma unroll
        for (int q = 0; q < 4; q++) {
            float v = (vv[q] - mn) * inv;
            int i = __float2int_rn(v * SUBSCALE);
            atomicAdd(&sh[i], 1.0f);
        }
    }
    __syncthreads();
    float* dst = g_part[b][blockIdx.x];
    for (int i = t; i < SUBN; i += blockDim.x) dst[i] = sh[i];
}

// 32768 threads; two threads per output element, 37 partials each, pair-combine.
__global__ void k_reduce() {
    __shared__ float s[256];
    int t = blockIdx.x * blockDim.x + threadIdx.x;   // 128*256 = 32768
    int o = t >> 1;                                   // output element 0..16383
    int half = t & 1;
    int b = o >> 13;                                  // /SUBN
    int e = o & (SUBN - 1);
    const float* p = &g_part[b][0][e];
    float sum = 0.0f;
    int k0 = half * 37;
    #pragma unroll 8
    for (int k = 0; k < 37; k++) sum += p[(k0 + k) * SUBN];
    s[threadIdx.x] = sum;
    __syncthreads();
    if ((threadIdx.x & 1) == 0)
        g_mom[b][e] = s[threadIdx.x] + s[threadIdx.x + 1];
}

// fine hist -> Gaussian conv (warp per bin, lane per tap) -> scan -> cdfn -> eq table
__global__ void k_post() {
    __shared__ float s_m[SUBN];        // 32KB
    __shared__ float s_scan[NB];
    __shared__ float s_cdfn[NB];
    const int b = blockIdx.x;
    const int tid = threadIdx.x;       // 1024 threads = 32 warps
    const int wid = tid >> 5;
    const int lane = tid & 31;
    for (int i = tid; i < SUBN; i += 1024) s_m[i] = g_mom[b][i];
    __syncthreads();

    #pragma unroll
    for (int jj = 0; jj < 8; jj++) {
        const int j = wid * 8 + jj;    // bin 0..255
        const int c = 32 * j;
        int mlo = (-MRAD < -c) ? -c : -MRAD;
        int mhi = (MRAD > 8160 - c) ? (8160 - c) : MRAD;
        float h = 0.0f;
        int m0 = mlo + lane;
        if (m0 <= mhi) {
            float fm = (float)m0;
            float w = __expf(-BETA * fm * fm);                       // tap weight
            float r = __expf(-BETA * (64.0f * fm + 1024.0f));        // step-32 ratio
            const float* p = s_m + c + m0;
            for (int m = m0; m <= mhi; m += 32) {
                h += w * (*p);
                p += 32;
                w *= r;
                r *= STEP32_C;
            }
        }
        #pragma unroll
        for (int o = 16; o; o >>= 1) h += __shfl_xor_sync(0xFFFFFFFFu, h, o);
        if (lane == 0) s_scan[j] = h;
    }
    __syncthreads();

    #pragma unroll
    for (int o = 1; o < NB; o <<= 1) {
        float add = (tid < NB && tid >= o) ? s_scan[tid - o] : 0.0f;
        __syncthreads();
        if (tid < NB) s_scan[tid] += add;
        __syncthreads();
    }
    if (tid < NB) {
        float total = s_scan[NB - 1];
        float invS  = 1.0f / (total + 1e-10f);
        float cdf   = s_scan[tid] * invS;
        float cdf0  = s_scan[0] * invS;
        s_cdfn[tid] = (cdf - cdf0) / (1.0f - cdf0 + 1e-10f);
    }
    __syncthreads();

    // Tabulate eq(v) on TABN grid points over v in [0,1]; 8 entries per thread.
    #pragma unroll
    for (int pp = 0; pp < TABN / 1024; pp++) {
        int p = pp * 1024 + tid;
        float v = (float)p * (1.0f / (float)(TABN - 1));
        int k = __float2int_rn(v * 255.0f);
        int jlo = k - RADIUS;
        float d0 = v - (float)jlo * INV255;
        float w = __expf(-5000.0f * d0 * d0);
        float r = __expf(TWO_A_D * d0 - A_D2);
        float num = 0.0f, den = 0.0f;
        #pragma unroll
        for (int s = 0; s < 2 * RADIUS + 1; s++) {
            int j = jlo + s;
            if (j >= 0 && j < NB) {
                num += w * s_cdfn[j];
                den += w;
            }
            w *= r;
            r *= RATIO_C;
        }
        g_eqtab[b][p] = num / (den + 1e-10f);
    }
}

__device__ __forceinline__ float eq_lerp(float xraw, float mn, float inv,
                                         const float* __restrict__ tb) {
    float v = (xraw - mn) * inv;
    float t = v * (float)(TABN - 1);
    int i0 = (int)t;
    float f = t - (float)i0;
    float e0 = __ldg(tb + i0);
    float e1 = __ldg(tb + i0 + 1);
    return fmaf(f, e1 - e0, e0);
}

__global__ void k_out(const float* __restrict__ x, float* __restrict__ out) {
    int idx = blockIdx.x * blockDim.x + threadIdx.x;   // 131072 output pixels
    int b = idx >> 16;
    int rem = idx & 0xFFFF;
    int oy = rem >> 8;
    int ox = rem & 255;
    const float* base = x + b * NPIX;
    float2 t0 = ((const float2*)(base + (2 * oy)     * HW))[ox];
    float2 t1 = ((const float2*)(base + (2 * oy + 1) * HW))[ox];

    const float mn  = g_scale[0];
    const float inv = g_scale[1];
    const float* tb = g_eqtab[b];
    float e = eq_lerp(t0.x, mn, inv, tb)
            + eq_lerp(t0.y, mn, inv, tb)
            + eq_lerp(t1.x, mn, inv, tb)
            + eq_lerp(t1.y, mn, inv, tb);
    out[idx] = (0.25f * e - 0.15f) / 0.1f;
}

extern "C" void kernel_launch(void* const* d_in, const int* in_sizes, int n_in,
                              void* d_out, int out_size) {
    const float* x = (const float*)d_in[0];
    float* out = (float*)d_out;
    k_minmax<<<NMM, 256>>>(x);
    k_hist<<<dim3(HBLKN, 2), 256>>>(x);
    k_reduce<<<128, 256>>>();
    k_post<<<2, 1024>>>();
    k_out<<<512, 256>>>(x, out);
}

// round 6
// speedup vs baseline: 4.4286x; 1.2879x over previous
#include <cuda_runtime.h>

// XrayTransforms: standardize -> soft-hist equalize -> 2x bilinear (=2x2 avg) -> normalize
// x: (2,1,512,512) f32, out: (2,1,256,256) f32
//
// Round 6: round-5 k_post (grid=2, issue-bound on 2 SMs) split into
// k_conv (16 blocks) / k_scan (2 blocks) / k_table (8 blocks).

#define NB 256
#define HW 512
#define NPIX (HW*HW)            // 262144 per batch
#define SUBN 8192
#define SUBSCALE 8160.0f        // 255*32 sub-bins across [0,1]
#define BETA 7.5091258e-5f      // A / 8160^2, A = 5000
#define MRAD 420                // conv radius in sub-bins (13.1 bins)
#define STEP32_C 0.85745500f    // exp(-2048*BETA) = exp(-2*A*Delta^2)
#define TABN 8192
#define NMM 128                 // minmax blocks
#define HBLKN 74                // hist blocks per batch
#define RADIUS 12
#define TWO_A_D  39.21568627450980f   // 2*A*Delta (Delta = 1/255)
#define A_D2     0.07689350249903883f // A*Delta^2
#define RATIO_C  0.85745500f          // exp(-2*A*Delta^2)
#define INV255   (1.0f/255.0f)

__device__ float g_pmin[NMM];
__device__ float g_pmax[NMM];
__device__ float g_scale[2];                 // [0]=min, [1]=1/(max-min+1e-6)
__device__ float g_part[2][HBLKN][SUBN];     // per-block fine-hist partials
__device__ float g_mom[2][SUBN];             // reduced fine hist
__device__ float g_hist[2][NB];
__device__ float g_cdfn[2][NB];
__device__ float g_eqtab[2][TABN];

__global__ void k_minmax(const float* __restrict__ x) {
    __shared__ float smn[256], smx[256];
    const float4* x4 = (const float4*)x;
    int base = blockIdx.x * 1024 + threadIdx.x;     // 131072 float4 / 128 blocks
    float mn = 1e30f, mx = -1e30f;
    #pragma unroll
    for (int q = 0; q < 4; q++) {
        float4 v = x4[base + q * 256];
        mn = fminf(mn, fminf(fminf(v.x, v.y), fminf(v.z, v.w)));
        mx = fmaxf(mx, fmaxf(fmaxf(v.x, v.y), fmaxf(v.z, v.w)));
    }
    smn[threadIdx.x] = mn; smx[threadIdx.x] = mx;
    __syncthreads();
    for (int o = 128; o; o >>= 1) {
        if (threadIdx.x < o) {
            smn[threadIdx.x] = fminf(smn[threadIdx.x], smn[threadIdx.x + o]);
            smx[threadIdx.x] = fmaxf(smx[threadIdx.x], smx[threadIdx.x + o]);
        }
        __syncthreads();
    }
    if (threadIdx.x == 0) { g_pmin[blockIdx.x] = smn[0]; g_pmax[blockIdx.x] = smx[0]; }
}

// 1 shared atomic per pixel into 8192 fine sub-bins; non-atomic flush to g_part.
__global__ void k_hist(const float* __restrict__ x) {
    __shared__ float sh[SUBN];                 // 32KB
    __shared__ float smm[256];
    const int t = threadIdx.x;
    smm[t] = (t < NMM) ? g_pmin[t] : 1e30f;
    __syncthreads();
    for (int o = 128; o; o >>= 1) { if (t < o) smm[t] = fminf(smm[t], smm[t + o]); __syncthreads(); }
    const float mn = smm[0];
    __syncthreads();
    smm[t] = (t < NMM) ? g_pmax[t] : -1e30f;
    __syncthreads();
    for (int o = 128; o; o >>= 1) { if (t < o) smm[t] = fmaxf(smm[t], smm[t + o]); __syncthreads(); }
    const float inv = 1.0f / (smm[0] - mn + 1e-6f);
    if (blockIdx.x == 0 && blockIdx.y == 0 && t == 0) { g_scale[0] = mn; g_scale[1] = inv; }
    __syncthreads();

    for (int i = t; i < SUBN; i += blockDim.x) sh[i] = 0.0f;
    __syncthreads();

    const int b = blockIdx.y;
    const float4* xb = (const float4*)(x + b * NPIX);
    const int n4 = NPIX / 4;
    const int stride = gridDim.x * blockDim.x;
    for (int idx = blockIdx.x * blockDim.x + t; idx < n4; idx += stride) {
        float4 p4 = xb[idx];
        float vv[4] = {p4.x, p4.y, p4.z, p4.w};
        #pragma unroll
        for (int q = 0; q < 4; q++) {
            float v = (vv[q] - mn) * inv;
            int i = __float2int_rn(v * SUBSCALE);
            atomicAdd(&sh[i], 1.0f);
        }
    }
    __syncthreads();
    float* dst = g_part[b][blockIdx.x];
    for (int i = t; i < SUBN; i += blockDim.x) dst[i] = sh[i];
}

// 32768 threads; two threads per output element, 37 partials each, pair-combine.
__global__ void k_reduce() {
    __shared__ float s[256];
    int t = blockIdx.x * blockDim.x + threadIdx.x;   // 128*256 = 32768
    int o = t >> 1;                                   // output element 0..16383
    int half = t & 1;
    int b = o >> 13;                                  // /SUBN
    int e = o & (SUBN - 1);
    const float* p = &g_part[b][0][e];
    float sum = 0.0f;
    int k0 = half * 37;
    #pragma unroll 8
    for (int k = 0; k < 37; k++) sum += p[(k0 + k) * SUBN];
    s[threadIdx.x] = sum;
    __syncthreads();
    if ((threadIdx.x & 1) == 0)
        g_mom[b][e] = s[threadIdx.x] + s[threadIdx.x + 1];
}

// Gaussian conv: warp per bin, lane per tap; taps straight from L2.
__global__ void k_conv() {
    const int b = blockIdx.y;
    const int wid = threadIdx.x >> 5;   // 8 warps
    const int lane = threadIdx.x & 31;
    const float* __restrict__ mom = g_mom[b];

    #pragma unroll
    for (int jj = 0; jj < 4; jj++) {
        const int j = blockIdx.x * 32 + wid * 4 + jj;   // bin 0..255
        const int c = 32 * j;
        int mlo = (-MRAD < -c) ? -c : -MRAD;
        int mhi = (MRAD > 8160 - c) ? (8160 - c) : MRAD;
        float h = 0.0f;
        int m0 = mlo + lane;
        if (m0 <= mhi) {
            float fm = (float)m0;
            float w = __expf(-BETA * fm * fm);                       // tap weight
            float r = __expf(-BETA * (64.0f * fm + 1024.0f));        // step-32 ratio
            const float* p = mom + c + m0;
            for (int m = m0; m <= mhi; m += 32) {
                h += w * __ldg(p);
                p += 32;
                w *= r;
                r *= STEP32_C;
            }
        }
        #pragma unroll
        for (int o = 16; o; o >>= 1) h += __shfl_xor_sync(0xFFFFFFFFu, h, o);
        if (lane == 0) g_hist[b][j] = h;
    }
}

__global__ void k_scan() {
    __shared__ float s[NB];
    const int b = blockIdx.x;
    const int t = threadIdx.x;
    s[t] = g_hist[b][t];
    __syncthreads();
    #pragma unroll
    for (int o = 1; o < NB; o <<= 1) {
        float add = (t >= o) ? s[t - o] : 0.0f;
        __syncthreads();
        s[t] += add;
        __syncthreads();
    }
    float total = s[NB - 1];
    float invS  = 1.0f / (total + 1e-10f);
    float cdf   = s[t] * invS;
    float cdf0  = s[0] * invS;
    g_cdfn[b][t] = (cdf - cdf0) / (1.0f - cdf0 + 1e-10f);
}

// Tabulate eq(v) on TABN grid points; 4 entries per thread, 8 blocks.
__global__ void k_table() {
    __shared__ float cdfn[NB];
    const int b = blockIdx.y;
    if (threadIdx.x < NB) cdfn[threadIdx.x] = g_cdfn[b][threadIdx.x];
    __syncthreads();

    #pragma unroll
    for (int pp = 0; pp < 4; pp++) {
        int p = blockIdx.x * 2048 + pp * 512 + threadIdx.x;   // 0..TABN-1
        float v = (float)p * (1.0f / (float)(TABN - 1));
        int k = __float2int_rn(v * 255.0f);
        int jlo = k - RADIUS;
        float d0 = v - (float)jlo * INV255;
        float w = __expf(-5000.0f * d0 * d0);
        float r = __expf(TWO_A_D * d0 - A_D2);
        float num = 0.0f, den = 0.0f;
        #pragma unroll
        for (int s = 0; s < 2 * RADIUS + 1; s++) {
            int j = jlo + s;
            if (j >= 0 && j < NB) {
                num += w * cdfn[j];
                den += w;
            }
            w *= r;
            r *= RATIO_C;
        }
        g_eqtab[b][p] = num / (den + 1e-10f);
    }
}

__device__ __forceinline__ float eq_lerp(float xraw, float mn, float inv,
                                         const float* __restrict__ tb) {
    float v = (xraw - mn) * inv;
    float t = v * (float)(TABN - 1);
    int i0 = (int)t;
    float f = t - (float)i0;
    float e0 = __ldg(tb + i0);
    float e1 = __ldg(tb + i0 + 1);
    return fmaf(f, e1 - e0, e0);
}

__global__ void k_out(const float* __restrict__ x, float* __restrict__ out) {
    int idx = blockIdx.x * blockDim.x + threadIdx.x;   // 131072 output pixels
    int b = idx >> 16;
    int rem = idx & 0xFFFF;
    int oy = rem >> 8;
    int ox = rem & 255;
    const float* base = x + b * NPIX;
    float2 t0 = ((const float2*)(base + (2 * oy)     * HW))[ox];
    float2 t1 = ((const float2*)(base + (2 * oy + 1) * HW))[ox];

    const float mn  = g_scale[0];
    const float inv = g_scale[1];
    const float* tb = g_eqtab[b];
    float e = eq_lerp(t0.x, mn, inv, tb)
            + eq_lerp(t0.y, mn, inv, tb)
            + eq_lerp(t1.x, mn, inv, tb)
            + eq_lerp(t1.y, mn, inv, tb);
    out[idx] = (0.25f * e - 0.15f) / 0.1f;
}

extern "C" void kernel_launch(void* const* d_in, const int* in_sizes, int n_in,
                              void* d_out, int out_size) {
    const float* x = (const float*)d_in[0];
    float* out = (float*)d_out;
    k_minmax<<<NMM, 256>>>(x);
    k_hist<<<dim3(HBLKN, 2), 256>>>(x);
    k_reduce<<<128, 256>>>();
    k_conv<<<dim3(8, 2), 256>>>();
    k_scan<<<2, NB>>>();
    k_table<<<dim3(4, 2), 512>>>();
    k_out<<<512, 256>>>(x, out);
}

// round 7
// speedup vs baseline: 5.6124x; 1.2673x over previous
#include <cuda_runtime.h>

// XrayTransforms: standardize -> soft-hist equalize -> 2x bilinear (=2x2 avg) -> normalize
// x: (2,1,512,512) f32, out: (2,1,256,256) f32
//
// Round 7: 5 launches.
//   k_minmax : block min/max partials + zeros g_mom
//   k_hist   : fine hist in smem, atomic flush to g_mom (counts exact in f32)
//   k_conv   : smem-staged, fixed-27-tap unrolled Gaussian conv, warp-per-bin
//   k_table  : redundant per-block scan -> cdfn -> eq table (8192 pts)
//   k_out    : 2x2 avg of table lerps + normalize

#define NB 256
#define HW 512
#define NPIX (HW*HW)            // 262144 per batch
#define SUBN 8192
#define SUBSCALE 8160.0f        // 255*32 sub-bins across [0,1]
#define BETA 7.5091258e-5f      // A / 8160^2, A = 5000
#define STEP32_C 0.85745500f    // exp(-2048*BETA) = exp(-2*A*Delta^2)
#define TABN 8192
#define NMM 128                 // minmax blocks
#define HBLKN 74                // hist blocks per batch
#define RADIUS 12
#define TWO_A_D  39.21568627450980f   // 2*A*Delta (Delta = 1/255)
#define A_D2     0.07689350249903883f // A*Delta^2
#define RATIO_C  0.85745500f          // exp(-2*A*Delta^2)
#define INV255   (1.0f/255.0f)
#define CWIN 1120               // conv smem window (needs 1088)

__device__ float g_pmin[NMM];
__device__ float g_pmax[NMM];
__device__ float g_scale[2];            // [0]=min, [1]=1/(max-min+1e-6)
__device__ float g_mom[2][SUBN];        // fine hist (atomic-accumulated)
__device__ float g_hist[2][NB];
__device__ float g_eqtab[2][TABN];

__global__ void k_minmax(const float* __restrict__ x) {
    __shared__ float smn[256], smx[256];
    // zero g_mom: 128 blocks x 128 elements
    if (threadIdx.x < 128)
        ((float*)g_mom)[blockIdx.x * 128 + threadIdx.x] = 0.0f;

    const float4* x4 = (const float4*)x;
    int base = blockIdx.x * 1024 + threadIdx.x;     // 131072 float4 / 128 blocks
    float mn = 1e30f, mx = -1e30f;
    #pragma unroll
    for (int q = 0; q < 4; q++) {
        float4 v = x4[base + q * 256];
        mn = fminf(mn, fminf(fminf(v.x, v.y), fminf(v.z, v.w)));
        mx = fmaxf(mx, fmaxf(fmaxf(v.x, v.y), fmaxf(v.z, v.w)));
    }
    smn[threadIdx.x] = mn; smx[threadIdx.x] = mx;
    __syncthreads();
    for (int o = 128; o; o >>= 1) {
        if (threadIdx.x < o) {
            smn[threadIdx.x] = fminf(smn[threadIdx.x], smn[threadIdx.x + o]);
            smx[threadIdx.x] = fmaxf(smx[threadIdx.x], smx[threadIdx.x + o]);
        }
        __syncthreads();
    }
    if (threadIdx.x == 0) { g_pmin[blockIdx.x] = smn[0]; g_pmax[blockIdx.x] = smx[0]; }
}

// 1 shared atomic per pixel into 8192 fine sub-bins; atomic flush to g_mom.
__global__ void k_hist(const float* __restrict__ x) {
    __shared__ float sh[SUBN];                 // 32KB
    __shared__ float smm[256];
    const int t = threadIdx.x;
    smm[t] = (t < NMM) ? g_pmin[t] : 1e30f;
    __syncthreads();
    for (int o = 128; o; o >>= 1) { if (t < o) smm[t] = fminf(smm[t], smm[t + o]); __syncthreads(); }
    const float mn = smm[0];
    __syncthreads();
    smm[t] = (t < NMM) ? g_pmax[t] : -1e30f;
    __syncthreads();
    for (int o = 128; o; o >>= 1) { if (t < o) smm[t] = fmaxf(smm[t], smm[t + o]); __syncthreads(); }
    const float inv = 1.0f / (smm[0] - mn + 1e-6f);
    if (blockIdx.x == 0 && blockIdx.y == 0 && t == 0) { g_scale[0] = mn; g_scale[1] = inv; }
    __syncthreads();

    for (int i = t; i < SUBN; i += blockDim.x) sh[i] = 0.0f;
    __syncthreads();

    const int b = blockIdx.y;
    const float4* xb = (const float4*)(x + b * NPIX);
    const int n4 = NPIX / 4;
    const int stride = gridDim.x * blockDim.x;
    for (int idx = blockIdx.x * blockDim.x + t; idx < n4; idx += stride) {
        float4 p4 = xb[idx];
        float vv[4] = {p4.x, p4.y, p4.z, p4.w};
        #pragma unroll
        for (int q = 0; q < 4; q++) {
            float v = (vv[q] - mn) * inv;
            int i = __float2int_rn(v * SUBSCALE);
            atomicAdd(&sh[i], 1.0f);
        }
    }
    __syncthreads();
    // counts are exact integers in f32 -> order-independent, deterministic
    float* dst = g_mom[b];
    for (int i = t; i < SUBN; i += blockDim.x) {
        float v = sh[i];
        if (v != 0.0f) atomicAdd(&dst[i], v);
    }
}

// Gaussian conv: smem-staged window, warp per bin, fixed 27 unrolled taps.
__global__ void k_conv() {
    __shared__ float s[CWIN];
    const int b = blockIdx.y;
    const int j0 = blockIdx.x * 8;          // 8 bins per block
    const int lo = 32 * j0 - 420;
    const int tid = threadIdx.x;            // 256 threads = 8 warps

    for (int i = tid; i < CWIN; i += 256) {
        int gi = lo + i;
        s[i] = (gi >= 0 && gi < SUBN) ? g_mom[b][gi] : 0.0f;
    }
    __syncthreads();

    const int wid = tid >> 5;
    const int lane = tid & 31;
    // lane handles taps m = -420+lane, step 32, 27 taps (max m=443; tail
    // weights <4e-7 relative, window staged/zero there).
    float fm = (float)(lane - 420);
    float w = __expf(-BETA * fm * fm);
    float r = __expf(-BETA * (64.0f * fm + 1024.0f));
    const float* p = s + 32 * wid + lane;   // = center(32*wid+420) + m
    float h = 0.0f;
    #pragma unroll
    for (int it = 0; it < 27; it++) {
        h += w * p[it * 32];
        w *= r;
        r *= STEP32_C;
    }
    #pragma unroll
    for (int o = 16; o; o >>= 1) h += __shfl_xor_sync(0xFFFFFFFFu, h, o);
    if (lane == 0) g_hist[b][j0 + wid] = h;
}

// Redundant per-block scan -> cdfn -> eq table.
__global__ void k_table() {
    __shared__ float s[NB];
    __shared__ float cdfn[NB];
    const int b = blockIdx.y;
    const int tid = threadIdx.x;            // 512 threads
    if (tid < NB) s[tid] = g_hist[b][tid];
    __syncthreads();
    #pragma unroll
    for (int o = 1; o < NB; o <<= 1) {
        float add = (tid < NB && tid >= o) ? s[tid - o] : 0.0f;
        __syncthreads();
        if (tid < NB) s[tid] += add;
        __syncthreads();
    }
    if (tid < NB) {
        float total = s[NB - 1];
        float invS  = 1.0f / (total + 1e-10f);
        float cdf   = s[tid] * invS;
        float cdf0  = s[0] * invS;
        cdfn[tid] = (cdf - cdf0) / (1.0f - cdf0 + 1e-10f);
    }
    __syncthreads();

    #pragma unroll
    for (int pp = 0; pp < 4; pp++) {
        int p = blockIdx.x * 2048 + pp * 512 + tid;   // 0..TABN-1
        float v = (float)p * (1.0f / (float)(TABN - 1));
        int k = __float2int_rn(v * 255.0f);
        int jlo = k - RADIUS;
        float d0 = v - (float)jlo * INV255;
        float w = __expf(-5000.0f * d0 * d0);
        float r = __expf(TWO_A_D * d0 - A_D2);
        float num = 0.0f, den = 0.0f;
        #pragma unroll
        for (int st = 0; st < 2 * RADIUS + 1; st++) {
            int j = jlo + st;
            if (j >= 0 && j < NB) {
                num += w * cdfn[j];
                den += w;
            }
            w *= r;
            r *= RATIO_C;
        }
        g_eqtab[b][p] = num / (den + 1e-10f);
    }
}

__device__ __forceinline__ float eq_lerp(float xraw, float mn, float inv,
                                         const float* __restrict__ tb) {
    float v = (xraw - mn) * inv;
    float t = v * (float)(TABN - 1);
    int i0 = (int)t;
    float f = t - (float)i0;
    float e0 = __ldg(tb + i0);
    float e1 = __ldg(tb + i0 + 1);
    return fmaf(f, e1 - e0, e0);
}

__global__ void k_out(const float* __restrict__ x, float* __restrict__ out) {
    int idx = blockIdx.x * blockDim.x + threadIdx.x;   // 131072 output pixels
    int b = idx >> 16;
    int rem = idx & 0xFFFF;
    int oy = rem >> 8;
    int ox = rem & 255;
    const float* base = x + b * NPIX;
    float2 t0 = ((const float2*)(base + (2 * oy)     * HW))[ox];
    float2 t1 = ((const float2*)(base + (2 * oy + 1) * HW))[ox];

    const float mn  = g_scale[0];
    const float inv = g_scale[1];
    const float* tb = g_eqtab[b];
    float e = eq_lerp(t0.x, mn, inv, tb)
            + eq_lerp(t0.y, mn, inv, tb)
            + eq_lerp(t1.x, mn, inv, tb)
            + eq_lerp(t1.y, mn, inv, tb);
    out[idx] = (0.25f * e - 0.15f) / 0.1f;
}

extern "C" void kernel_launch(void* const* d_in, const int* in_sizes, int n_in,
                              void* d_out, int out_size) {
    const float* x = (const float*)d_in[0];
    float* out = (float*)d_out;
    k_minmax<<<NMM, 256>>>(x);
    k_hist<<<dim3(HBLKN, 2), 256>>>(x);
    k_conv<<<dim3(32, 2), 256>>>();
    k_table<<<dim3(4, 2), 512>>>();
    k_out<<<512, 256>>>(x, out);
}

// round 8
// speedup vs baseline: 5.6204x; 1.0014x over previous
#include <cuda_runtime.h>

// XrayTransforms: standardize -> soft-hist equalize -> 2x bilinear (=2x2 avg) -> normalize
// x: (2,1,512,512) f32, out: (2,1,256,256) f32
//
// Round 8: k_table widened to 32 blocks, 1 entry/thread, branch-free taps
// via padded cdfn + mask arrays. Rest unchanged from round 7.

#define NB 256
#define HW 512
#define NPIX (HW*HW)            // 262144 per batch
#define SUBN 8192
#define SUBSCALE 8160.0f        // 255*32 sub-bins across [0,1]
#define BETA 7.5091258e-5f      // A / 8160^2, A = 5000
#define STEP32_C 0.85745500f    // exp(-2048*BETA) = exp(-2*A*Delta^2)
#define TABN 8192
#define NMM 128                 // minmax blocks
#define HBLKN 74                // hist blocks per batch
#define RADIUS 12
#define TWO_A_D  39.21568627450980f   // 2*A*Delta (Delta = 1/255)
#define A_D2     0.07689350249903883f // A*Delta^2
#define RATIO_C  0.85745500f          // exp(-2*A*Delta^2)
#define INV255   (1.0f/255.0f)
#define CWIN 1120               // conv smem window (needs 1088)
#define PAD (NB + 2*RADIUS)     // 280: padded cdfn/mask arrays

__device__ float g_pmin[NMM];
__device__ float g_pmax[NMM];
__device__ float g_scale[2];            // [0]=min, [1]=1/(max-min+1e-6)
__device__ float g_mom[2][SUBN];        // fine hist (atomic-accumulated)
__device__ float g_hist[2][NB];
__device__ float g_eqtab[2][TABN];

__global__ void k_minmax(const float* __restrict__ x) {
    __shared__ float smn[256], smx[256];
    // zero g_mom: 128 blocks x 128 elements
    if (threadIdx.x < 128)
        ((float*)g_mom)[blockIdx.x * 128 + threadIdx.x] = 0.0f;

    const float4* x4 = (const float4*)x;
    int base = blockIdx.x * 1024 + threadIdx.x;     // 131072 float4 / 128 blocks
    float mn = 1e30f, mx = -1e30f;
    #pragma unroll
    for (int q = 0; q < 4; q++) {
        float4 v = x4[base + q * 256];
        mn = fminf(mn, fminf(fminf(v.x, v.y), fminf(v.z, v.w)));
        mx = fmaxf(mx, fmaxf(fmaxf(v.x, v.y), fmaxf(v.z, v.w)));
    }
    smn[threadIdx.x] = mn; smx[threadIdx.x] = mx;
    __syncthreads();
    for (int o = 128; o; o >>= 1) {
        if (threadIdx.x < o) {
            smn[threadIdx.x] = fminf(smn[threadIdx.x], smn[threadIdx.x + o]);
            smx[threadIdx.x] = fmaxf(smx[threadIdx.x], smx[threadIdx.x + o]);
        }
        __syncthreads();
    }
    if (threadIdx.x == 0) { g_pmin[blockIdx.x] = smn[0]; g_pmax[blockIdx.x] = smx[0]; }
}

// 1 shared atomic per pixel into 8192 fine sub-bins; atomic flush to g_mom.
__global__ void k_hist(const float* __restrict__ x) {
    __shared__ float sh[SUBN];                 // 32KB
    __shared__ float smm[256];
    const int t = threadIdx.x;
    smm[t] = (t < NMM) ? g_pmin[t] : 1e30f;
    __syncthreads();
    for (int o = 128; o; o >>= 1) { if (t < o) smm[t] = fminf(smm[t], smm[t + o]); __syncthreads(); }
    const float mn = smm[0];
    __syncthreads();
    smm[t] = (t < NMM) ? g_pmax[t] : -1e30f;
    __syncthreads();
    for (int o = 128; o; o >>= 1) { if (t < o) smm[t] = fmaxf(smm[t], smm[t + o]); __syncthreads(); }
    const float inv = 1.0f / (smm[0] - mn + 1e-6f);
    if (blockIdx.x == 0 && blockIdx.y == 0 && t == 0) { g_scale[0] = mn; g_scale[1] = inv; }
    __syncthreads();

    for (int i = t; i < SUBN; i += blockDim.x) sh[i] = 0.0f;
    __syncthreads();

    const int b = blockIdx.y;
    const float4* xb = (const float4*)(x + b * NPIX);
    const int n4 = NPIX / 4;
    const int stride = gridDim.x * blockDim.x;
    for (int idx = blockIdx.x * blockDim.x + t; idx < n4; idx += stride) {
        float4 p4 = xb[idx];
        float vv[4] = {p4.x, p4.y, p4.z, p4.w};
        #pragma unroll
        for (int q = 0; q < 4; q++) {
            float v = (vv[q] - mn) * inv;
            int i = __float2int_rn(v * SUBSCALE);
            atomicAdd(&sh[i], 1.0f);
        }
    }
    __syncthreads();
    // counts are exact integers in f32 -> order-independent, deterministic
    float* dst = g_mom[b];
    for (int i = t; i < SUBN; i += blockDim.x) {
        float v = sh[i];
        if (v != 0.0f) atomicAdd(&dst[i], v);
    }
}

// Gaussian conv: smem-staged window, warp per bin, fixed 27 unrolled taps.
__global__ void k_conv() {
    __shared__ float s[CWIN];
    const int b = blockIdx.y;
    const int j0 = blockIdx.x * 8;          // 8 bins per block
    const int lo = 32 * j0 - 420;
    const int tid = threadIdx.x;            // 256 threads = 8 warps

    for (int i = tid; i < CWIN; i += 256) {
        int gi = lo + i;
        s[i] = (gi >= 0 && gi < SUBN) ? g_mom[b][gi] : 0.0f;
    }
    __syncthreads();

    const int wid = tid >> 5;
    const int lane = tid & 31;
    float fm = (float)(lane - 420);
    float w = __expf(-BETA * fm * fm);
    float r = __expf(-BETA * (64.0f * fm + 1024.0f));
    const float* p = s + 32 * wid + lane;
    float h = 0.0f;
    #pragma unroll
    for (int it = 0; it < 27; it++) {
        h += w * p[it * 32];
        w *= r;
        r *= STEP32_C;
    }
    #pragma unroll
    for (int o = 16; o; o >>= 1) h += __shfl_xor_sync(0xFFFFFFFFu, h, o);
    if (lane == 0) g_hist[b][j0 + wid] = h;
}

// Redundant per-block scan -> cdfn (padded) -> 1 eq-table entry per thread.
__global__ void k_table() {
    __shared__ float s[NB];
    __shared__ float c_pad[PAD];   // cdfn with RADIUS zero-pad each side
    __shared__ float m_pad[PAD];   // validity mask
    const int b = blockIdx.y;
    const int tid = threadIdx.x;   // 512 threads

    for (int i = tid; i < PAD; i += 512) { c_pad[i] = 0.0f; m_pad[i] = 0.0f; }
    if (tid < NB) s[tid] = g_hist[b][tid];
    __syncthreads();
    #pragma unroll
    for (int o = 1; o < NB; o <<= 1) {
        float add = (tid < NB && tid >= o) ? s[tid - o] : 0.0f;
        __syncthreads();
        if (tid < NB) s[tid] += add;
        __syncthreads();
    }
    if (tid < NB) {
        float total = s[NB - 1];
        float invS  = 1.0f / (total + 1e-10f);
        float cdf   = s[tid] * invS;
        float cdf0  = s[0] * invS;
        c_pad[tid + RADIUS] = (cdf - cdf0) / (1.0f - cdf0 + 1e-10f);
        m_pad[tid + RADIUS] = 1.0f;
    }
    __syncthreads();

    int p = blockIdx.x * 512 + tid;        // 0..TABN-1 (grid.x = 16)
    float v = (float)p * (1.0f / (float)(TABN - 1));
    int k = __float2int_rn(v * 255.0f);
    int jlo = k - RADIUS;
    float d0 = v - (float)jlo * INV255;
    float w = __expf(-5000.0f * d0 * d0);
    float r = __expf(TWO_A_D * d0 - A_D2);
    float num = 0.0f, den = 0.0f;
    const float* cp = c_pad + jlo + RADIUS;   // index 0..24 valid (padded)
    const float* mp = m_pad + jlo + RADIUS;
    #pragma unroll
    for (int st = 0; st < 2 * RADIUS + 1; st++) {
        num = fmaf(w, cp[st], num);
        den = fmaf(w, mp[st], den);
        w *= r;
        r *= RATIO_C;
    }
    g_eqtab[b][p] = num / (den + 1e-10f);
}

__device__ __forceinline__ float eq_lerp(float xraw, float mn, float inv,
                                         const float* __restrict__ tb) {
    float v = (xraw - mn) * inv;
    float t = v * (float)(TABN - 1);
    int i0 = (int)t;
    float f = t - (float)i0;
    float e0 = __ldg(tb + i0);
    float e1 = __ldg(tb + i0 + 1);
    return fmaf(f, e1 - e0, e0);
}

__global__ void k_out(const float* __restrict__ x, float* __restrict__ out) {
    int idx = blockIdx.x * blockDim.x + threadIdx.x;   // 131072 output pixels
    int b = idx >> 16;
    int rem = idx & 0xFFFF;
    int oy = rem >> 8;
    int ox = rem & 255;
    const float* base = x + b * NPIX;
    float2 t0 = ((const float2*)(base + (2 * oy)     * HW))[ox];
    float2 t1 = ((const float2*)(base + (2 * oy + 1) * HW))[ox];

    const float mn  = g_scale[0];
    const float inv = g_scale[1];
    const float* tb = g_eqtab[b];
    float e = eq_lerp(t0.x, mn, inv, tb)
            + eq_lerp(t0.y, mn, inv, tb)
            + eq_lerp(t1.x, mn, inv, tb)
            + eq_lerp(t1.y, mn, inv, tb);
    out[idx] = (0.25f * e - 0.15f) / 0.1f;
}

extern "C" void kernel_launch(void* const* d_in, const int* in_sizes, int n_in,
                              void* d_out, int out_size) {
    const float* x = (const float*)d_in[0];
    float* out = (float*)d_out;
    k_minmax<<<NMM, 256>>>(x);
    k_hist<<<dim3(HBLKN, 2), 256>>>(x);
    k_conv<<<dim3(32, 2), 256>>>();
    k_table<<<dim3(16, 2), 512>>>();
    k_out<<<512, 256>>>(x, out);
}